// round 17
// baseline (speedup 1.0000x reference)
#include <cuda_runtime.h>
#include <cuda_bf16.h>
#include <cuda_fp16.h>
#include <math.h>
#include <stdint.h>

#define B_  4
#define T_  2048
#define D_  1024
#define NH_ 16
#define HS_ 64
#define NBIAS (2*T_ - 1)   // 4095
#define M_  (B_*T_)        // 8192
#define LOG2E 1.4426950408889634f

// ---------------- scratch (device globals: no allocation allowed) ----------
__device__ __half g_A1h [M_*(size_t)D_];     // queries fp16
__device__ __half g_AO1h[M_*(size_t)D_];     // attn-out fp16
__device__ __half g_W1  [4*(size_t)D_*D_];   // weights fp16
__device__ __half g_QKV1[3*(size_t)NH_*B_*T_*HS_]; // fp16 [z][bh][t][hs]
__device__ float g_bias[NH_*NBIAS];          // bias table, pre-scaled by log2(e)

#define TQ1 ((size_t)NH_*B_*T_*HS_)
#define WOFF1 ((size_t)D_*D_)

// ============================ PTX helpers ==================================
__device__ __forceinline__ uint32_t smem_u32(const void* p) {
    uint32_t a;
    asm("{ .reg .u64 t; cvta.to.shared.u64 t, %1; cvt.u32.u64 %0, t; }" : "=r"(a) : "l"(p));
    return a;
}
#define CP_ASYNC16(dst, src) \
    asm volatile("cp.async.cg.shared.global [%0], [%1], 16;" :: "r"(dst), "l"(src) : "memory")
#define CP_COMMIT() asm volatile("cp.async.commit_group;" ::: "memory")
#define CP_WAIT2()  asm volatile("cp.async.wait_group 2;" ::: "memory")
#define CP_WAIT3()  asm volatile("cp.async.wait_group 3;" ::: "memory")
#define CP_WAIT4()  asm volatile("cp.async.wait_group 4;" ::: "memory")

#define LDMATRIX_X4(r0, r1, r2, r3, addr) \
    asm volatile("ldmatrix.sync.aligned.m8n8.x4.shared.b16 {%0,%1,%2,%3}, [%4];" \
                 : "=r"(r0), "=r"(r1), "=r"(r2), "=r"(r3) : "r"(addr))
#define LDMATRIX_X4_T(r0, r1, r2, r3, addr) \
    asm volatile("ldmatrix.sync.aligned.m8n8.x4.trans.shared.b16 {%0,%1,%2,%3}, [%4];" \
                 : "=r"(r0), "=r"(r1), "=r"(r2), "=r"(r3) : "r"(addr))

#define MMA_F16(c, a, b0, b1) \
    asm volatile("mma.sync.aligned.m16n8k16.row.col.f32.f16.f16.f32 " \
                 "{%0,%1,%2,%3}, {%4,%5,%6,%7}, {%8,%9}, {%0,%1,%2,%3};" \
                 : "+f"((c)[0]), "+f"((c)[1]), "+f"((c)[2]), "+f"((c)[3]) \
                 : "r"((a)[0]), "r"((a)[1]), "r"((a)[2]), "r"((a)[3]), "r"(b0), "r"(b1))

__device__ __forceinline__ uint32_t packh(float a, float b) {
    __half2 v = __floats2half2_rn(a, b);
    return *(uint32_t*)&v;
}
__device__ __forceinline__ float ex2a(float x) {
    float y;
    asm("ex2.approx.f32 %0, %1;" : "=f"(y) : "f"(x));
    return y;
}

// ================== bias bucketing =========================================
__device__ __forceinline__ int bucket_of(int rp) {
    int b = (rp > 0) ? 16 : 0;
    int a = rp < 0 ? -rp : rp;
    if (a < 8) return b + a;
    double v = 7.0 + (log((double)a / 7.0) / log(128.0 / 7.0)) * 8.0;
    int large = (int)v;
    if (large > 15) large = 15;
    return b + large;
}

// ========= fused prep v2: wide converts (16 floats/thread) + bias table ====
#define NFQ ((size_t)M_ * D_)          // 8,388,608 query floats
#define NFW ((size_t)D_ * D_)          // 1,048,576 per weight
#define NCV ((int)((NFQ + 4 * NFW) / 16))   // 786,432 convert threads
#define NB1 (NH_ * NBIAS)
#define NPREP (NCV + NB1)

__global__ void prep_fused(const float* __restrict__ q,
                           const float* __restrict__ w0, const float* __restrict__ w1,
                           const float* __restrict__ w2, const float* __restrict__ w3,
                           const float* __restrict__ rel_emb,
                           __half* __restrict__ outA, __half* __restrict__ outW,
                           float* __restrict__ btab) {
    int i = blockIdx.x * blockDim.x + threadIdx.x;
    if (i >= NPREP) return;
    if (i >= NCV) {                     // bias-table element (log2-domain)
        int idx = i - NCV;
        int h = idx / NBIAS, x = idx % NBIAS;
        btab[idx] = rel_emb[bucket_of(x - (T_ - 1)) * NH_ + h] * LOG2E;
        return;
    }
    size_t f = (size_t)i * 16;          // first float handled by this thread
    const float* src;
    __half* dst;
    if (f < NFQ) { src = q + f; dst = outA + f; }
    else {
        size_t f2 = f - NFQ;
        int wsel = (int)(f2 >> 20);     // / (1024*1024)
        size_t off = f2 & (NFW - 1);
        src = (wsel == 0) ? w0 + off : (wsel == 1) ? w1 + off
            : (wsel == 2) ? w2 + off : w3 + off;
        dst = outW + (size_t)wsel * WOFF1 + off;
    }
    float4 v0 = ((const float4*)src)[0];
    float4 v1 = ((const float4*)src)[1];
    float4 v2 = ((const float4*)src)[2];
    float4 v3 = ((const float4*)src)[3];
    uint4 o0, o1;
    o0.x = packh(v0.x, v0.y); o0.y = packh(v0.z, v0.w);
    o0.z = packh(v1.x, v1.y); o0.w = packh(v1.z, v1.w);
    o1.x = packh(v2.x, v2.y); o1.y = packh(v2.z, v2.w);
    o1.z = packh(v3.x, v3.y); o1.w = packh(v3.z, v3.w);
    ((uint4*)dst)[0] = o0;
    ((uint4*)dst)[1] = o1;
}

// ================== fp16 GEMM (single-term, 4-stage pipeline) ==============
#define GS6 4
#define TB6 8192
#define GIT6 32
#define GEMM6_SMEM (GS6 * 2 * TB6)   // 64KB

template <int SPLITOUT>
__global__ __launch_bounds__(256, 2)
void gemm_hmma6(const __half* __restrict__ A, const __half* __restrict__ W0,
                float* __restrict__ outf, __half* __restrict__ outq) {
    extern __shared__ char sm6[];
    const uint32_t sb = smem_u32(sm6);

    const int tid  = threadIdx.x;
    const int w    = tid >> 5;
    const int lane = tid & 31;
    const int wm   = w & 1;
    const int wn   = w >> 1;
    const int m0   = blockIdx.y * 128;
    const int n0   = blockIdx.x * 128;
    const int z    = blockIdx.z;
    const __half* W = W0 + (size_t)z * WOFF1;

    float acc[4][4][4];
#pragma unroll
    for (int i = 0; i < 4; i++)
#pragma unroll
        for (int j = 0; j < 4; j++)
#pragma unroll
            for (int q = 0; q < 4; q++) acc[i][j][q] = 0.f;

    auto load_stage = [&](int it) {
        const uint32_t st = sb + (uint32_t)(it & 3) * (2 * TB6);
        const int kb = it * 32;
#pragma unroll
        for (int j = 0; j < 2; j++) {
            int idx = tid * 2 + j;
            int row = idx >> 2, u = idx & 3;
            uint32_t off = row * 64 + ((u ^ ((row >> 1) & 3)) << 4);
            CP_ASYNC16(st + off,       (const void*)(A + (size_t)(m0 + row) * D_ + kb + u * 8));
            CP_ASYNC16(st + TB6 + off, (const void*)(W + (size_t)(n0 + row) * D_ + kb + u * 8));
        }
        CP_COMMIT();
    };

    load_stage(0);
    load_stage(1);
    load_stage(2);

    for (int it = 0; it < GIT6; it++) {
        CP_WAIT2();
        __syncthreads();
        if (it + 3 < GIT6) load_stage(it + 3);
        else CP_COMMIT();

        const uint32_t aB = sb + (uint32_t)(it & 3) * (2 * TB6);
        const uint32_t wB = aB + TB6;

#pragma unroll
        for (int ks = 0; ks < 2; ks++) {
            uint32_t a[4][4];
#pragma unroll
            for (int fm = 0; fm < 4; fm++) {
                int row = wm * 64 + fm * 16 + (lane & 15);
                int u = ks * 2 + (lane >> 4);
                uint32_t off = row * 64 + ((u ^ ((row >> 1) & 3)) << 4);
                LDMATRIX_X4(a[fm][0], a[fm][1], a[fm][2], a[fm][3], aB + off);
            }
            uint32_t b[2][4];
#pragma unroll
            for (int fp = 0; fp < 2; fp++) {
                int n = wn * 32 + fp * 16 + (lane & 7) + ((lane >> 4) << 3);
                int u = ks * 2 + ((lane >> 3) & 1);
                uint32_t off = n * 64 + ((u ^ ((n >> 1) & 3)) << 4);
                LDMATRIX_X4(b[fp][0], b[fp][1], b[fp][2], b[fp][3], wB + off);
            }
#pragma unroll
            for (int fm = 0; fm < 4; fm++)
#pragma unroll
                for (int fp = 0; fp < 2; fp++) {
                    MMA_F16(acc[fm][fp * 2 + 0], a[fm], b[fp][0], b[fp][1]);
                    MMA_F16(acc[fm][fp * 2 + 1], a[fm], b[fp][2], b[fp][3]);
                }
        }
    }

    const int cr = lane >> 2;
    const int cc = 2 * (lane & 3);
    const float sc = (SPLITOUT && blockIdx.z == 0) ? (0.125f * LOG2E) : 1.f;
#pragma unroll
    for (int fm = 0; fm < 4; fm++) {
        int r = m0 + wm * 64 + fm * 16 + cr;
#pragma unroll
        for (int fn = 0; fn < 4; fn++) {
            int col = n0 + wn * 32 + fn * 8 + cc;
            if (SPLITOUT) {
                int bb = r >> 11, t = r & (T_ - 1);
                int hh = col >> 6, hs = col & 63;
                size_t base = (((size_t)z * (B_ * NH_) + bb * NH_ + hh) * T_ + t) * HS_ + hs;
                *(__half2*)(outq + base) =
                    __floats2half2_rn(acc[fm][fn][0] * sc, acc[fm][fn][1] * sc);
                *(__half2*)(outq + base + 8 * HS_) =
                    __floats2half2_rn(acc[fm][fn][2] * sc, acc[fm][fn][3] * sc);
            } else {
                *(float2*)(outf + (size_t)r * D_ + col) =
                    make_float2(acc[fm][fn][0], acc[fm][fn][1]);
                *(float2*)(outf + (size_t)(r + 8) * D_ + col) =
                    make_float2(acc[fm][fn][2], acc[fm][fn][3]);
            }
        }
    }
}

// ================== fp16 flash attention (Q frags in registers) ============
#define QT 128
#define KT 64
#define KVS 5
#define ASM_Q 0u
#define ASM_KV 16384u
#define KVST 16384u
#define ATTN_SMEM (16384 + KVS * 16384)    // 96KB
#define NKT (T_ / KT)                      // 32

__global__ __launch_bounds__(256, 2)
void attn_hmma(const __half* __restrict__ QKV, const float* __restrict__ btab,
               __half* __restrict__ out1) {
    extern __shared__ char sm[];
    const uint32_t sb = smem_u32(sm);

    const int tid  = threadIdx.x;
    const int w    = tid >> 5;
    const int lane = tid & 31;
    const int bh = blockIdx.y;
    const int h  = bh & (NH_ - 1);
    const int b  = bh >> 4;
    const int q0 = blockIdx.x * QT;

    const __half* Qq = QKV + (size_t)bh * T_ * HS_;
    const __half* Kq = QKV + TQ1 + (size_t)bh * T_ * HS_;
    const __half* Vq = QKV + 2 * TQ1 + (size_t)bh * T_ * HS_;
    const float* bias_h = btab + h * NBIAS + (T_ - 1);
    const float bias_lo = btab[h * NBIAS];
    const float bias_hi = btab[h * NBIAS + NBIAS - 1];
    const int wr0 = q0 + w * 16;

#pragma unroll
    for (int j = 0; j < 4; j++) {
        int idx = tid * 4 + j;
        int row = idx >> 3, u = idx & 7;
        uint32_t dst = sb + ASM_Q + row * 128 + ((u ^ (row & 7)) << 4);
        CP_ASYNC16(dst, (const void*)(Qq + (size_t)(q0 + row) * HS_ + u * 8));
    }
    CP_COMMIT();

    auto load_kv = [&](int t) {
        const uint32_t st = sb + ASM_KV + (uint32_t)(t % KVS) * KVST;
        const int k0 = t * KT;
#pragma unroll
        for (int j = 0; j < 2; j++) {
            int idx = tid * 2 + j;
            int row = idx >> 3, u = idx & 7;
            uint32_t off = row * 128 + ((u ^ (row & 7)) << 4);
            const size_t goff = (size_t)(k0 + row) * HS_ + u * 8;
            CP_ASYNC16(st + off,        (const void*)(Kq + goff));
            CP_ASYNC16(st + 8192 + off, (const void*)(Vq + goff));
        }
        CP_COMMIT();
    };

    load_kv(0);
    load_kv(1);
    load_kv(2);
    load_kv(3);

    // ---- hoist Q fragments into registers (tile-invariant) ----
    uint32_t qf[4][4];
    {
        CP_WAIT4();
        __syncthreads();
        const int row = w * 16 + (lane & 15);
#pragma unroll
        for (int u = 0; u < 4; u++) {
            int un = 2 * u + (lane >> 4);
            uint32_t ad = sb + ASM_Q + row * 128 + ((un ^ (row & 7)) << 4);
            LDMATRIX_X4(qf[u][0], qf[u][1], qf[u][2], qf[u][3], ad);
        }
    }

    float ofr[8][4];
    float mrow[2] = {-1e30f, -1e30f};
    float lrow[2] = {0.f, 0.f};
#pragma unroll
    for (int j = 0; j < 8; j++)
#pragma unroll
        for (int q = 0; q < 4; q++) ofr[j][q] = 0.f;

    for (int t = 0; t < NKT; t++) {
        CP_WAIT3();
        __syncthreads();
        if (t + 4 < NKT) load_kv(t + 4);
        else CP_COMMIT();

        const uint32_t kB = sb + ASM_KV + (uint32_t)(t % KVS) * KVST;
        const uint32_t vB = kB + 8192;
        const int k0 = t * KT;

        float sf[8][4];
#pragma unroll
        for (int j = 0; j < 8; j++)
#pragma unroll
            for (int q = 0; q < 4; q++) sf[j][q] = 0.f;

#pragma unroll
        for (int u = 0; u < 4; u++) {
#pragma unroll
            for (int fp = 0; fp < 4; fp++) {
                int n = fp * 16 + (lane & 7) + ((lane >> 4) << 3);
                int un = 2 * u + ((lane >> 3) & 1);
                uint32_t b0, b1, b2, b3;
                uint32_t bd = kB + n * 128 + ((un ^ (n & 7)) << 4);
                LDMATRIX_X4(b0, b1, b2, b3, bd);
                MMA_F16(sf[2 * fp + 0], qf[u], b0, b1);
                MMA_F16(sf[2 * fp + 1], qf[u], b2, b3);
            }
        }

        if (k0 + KT - 1 - wr0 <= -128) {
#pragma unroll
            for (int j = 0; j < 8; j++) {
                sf[j][0] += bias_lo; sf[j][1] += bias_lo;
                sf[j][2] += bias_lo; sf[j][3] += bias_lo;
            }
        } else if (k0 - wr0 - 15 >= 128) {
#pragma unroll
            for (int j = 0; j < 8; j++) {
                sf[j][0] += bias_hi; sf[j][1] += bias_hi;
                sf[j][2] += bias_hi; sf[j][3] += bias_hi;
            }
        } else {
            const int r0g = q0 + w * 16 + (lane >> 2);
#pragma unroll
            for (int j = 0; j < 8; j++) {
                int dk = k0 + 8 * j + 2 * (lane & 3) - r0g;
                sf[j][0] += bias_h[dk];
                sf[j][1] += bias_h[dk + 1];
                sf[j][2] += bias_h[dk - 8];
                sf[j][3] += bias_h[dk - 7];
            }
        }

        float mt0 = -1e30f, mt1 = -1e30f;
#pragma unroll
        for (int j = 0; j < 8; j++) {
            mt0 = fmaxf(mt0, fmaxf(sf[j][0], sf[j][1]));
            mt1 = fmaxf(mt1, fmaxf(sf[j][2], sf[j][3]));
        }
        mt0 = fmaxf(mt0, __shfl_xor_sync(0xffffffffu, mt0, 1));
        mt0 = fmaxf(mt0, __shfl_xor_sync(0xffffffffu, mt0, 2));
        mt1 = fmaxf(mt1, __shfl_xor_sync(0xffffffffu, mt1, 1));
        mt1 = fmaxf(mt1, __shfl_xor_sync(0xffffffffu, mt1, 2));

        bool keep = __all_sync(0xffffffffu, (mt0 <= mrow[0]) & (mt1 <= mrow[1]));
        if (!keep) {
            float mn0 = fmaxf(mrow[0], mt0), mn1 = fmaxf(mrow[1], mt1);
            float alpha0 = ex2a(mrow[0] - mn0), alpha1 = ex2a(mrow[1] - mn1);
            mrow[0] = mn0; mrow[1] = mn1;
            lrow[0] *= alpha0; lrow[1] *= alpha1;
#pragma unroll
            for (int j = 0; j < 8; j++) {
                ofr[j][0] *= alpha0; ofr[j][1] *= alpha0;
                ofr[j][2] *= alpha1; ofr[j][3] *= alpha1;
            }
        }

        float ls0 = 0.f, ls1 = 0.f;
#pragma unroll
        for (int j = 0; j < 8; j++) {
            sf[j][0] = ex2a(sf[j][0] - mrow[0]);
            sf[j][1] = ex2a(sf[j][1] - mrow[0]);
            sf[j][2] = ex2a(sf[j][2] - mrow[1]);
            sf[j][3] = ex2a(sf[j][3] - mrow[1]);
            ls0 += sf[j][0] + sf[j][1];
            ls1 += sf[j][2] + sf[j][3];
        }
        ls0 += __shfl_xor_sync(0xffffffffu, ls0, 1);
        ls0 += __shfl_xor_sync(0xffffffffu, ls0, 2);
        ls1 += __shfl_xor_sync(0xffffffffu, ls1, 1);
        ls1 += __shfl_xor_sync(0xffffffffu, ls1, 2);
        lrow[0] += ls0;
        lrow[1] += ls1;

#pragma unroll
        for (int kk = 0; kk < 4; kk++) {
            uint32_t ph[4];
            ph[0] = packh(sf[2 * kk][0],     sf[2 * kk][1]);
            ph[1] = packh(sf[2 * kk][2],     sf[2 * kk][3]);
            ph[2] = packh(sf[2 * kk + 1][0], sf[2 * kk + 1][1]);
            ph[3] = packh(sf[2 * kk + 1][2], sf[2 * kk + 1][3]);
            const int g = lane >> 3;
            const int rowv = kk * 16 + ((g & 1) << 3) + (lane & 7);
#pragma unroll
            for (int fb = 0; fb < 4; fb++) {
                int unit = fb * 2 + (g >> 1);
                uint32_t v0, v1, v2, v3;
                uint32_t av = vB + rowv * 128 + ((unit ^ (rowv & 7)) << 4);
                LDMATRIX_X4_T(v0, v1, v2, v3, av);
                MMA_F16(ofr[2 * fb + 0], ph, v0, v1);
                MMA_F16(ofr[2 * fb + 1], ph, v2, v3);
            }
        }
    }

    const float inv0 = 1.f / lrow[0], inv1 = 1.f / lrow[1];
    const int r0 = q0 + w * 16 + (lane >> 2), r1 = r0 + 8;
    __half* row0 = out1 + (size_t)(b * T_ + r0) * D_;
    __half* row1 = out1 + (size_t)(b * T_ + r1) * D_;
#pragma unroll
    for (int j = 0; j < 8; j++) {
        int col = h * HS_ + 8 * j + 2 * (lane & 3);
        *(uint32_t*)(row0 + col) = packh(ofr[j][0] * inv0, ofr[j][1] * inv0);
        *(uint32_t*)(row1 + col) = packh(ofr[j][2] * inv1, ofr[j][3] * inv1);
    }
}

// ================== launch ==================================================
extern "C" void kernel_launch(void* const* d_in, const int* in_sizes, int n_in,
                              void* d_out, int out_size) {
    const float* queries = (const float*)d_in[0];
    const float* Wq      = (const float*)d_in[1];
    const float* Wk      = (const float*)d_in[2];
    const float* Wv      = (const float*)d_in[3];
    const float* Wo      = (const float*)d_in[4];
    const float* rel_emb = (const float*)d_in[5];
    float* out = (float*)d_out;

    __half *gA1h, *gAO1h, *gW1, *gQKV1;
    float *gB;
    cudaGetSymbolAddress((void**)&gA1h,  g_A1h);
    cudaGetSymbolAddress((void**)&gAO1h, g_AO1h);
    cudaGetSymbolAddress((void**)&gW1,   g_W1);
    cudaGetSymbolAddress((void**)&gQKV1, g_QKV1);
    cudaGetSymbolAddress((void**)&gB,    g_bias);

    cudaFuncSetAttribute(attn_hmma, cudaFuncAttributeMaxDynamicSharedMemorySize, ATTN_SMEM);
    cudaFuncSetAttribute(gemm_hmma6<0>, cudaFuncAttributeMaxDynamicSharedMemorySize, GEMM6_SMEM);
    cudaFuncSetAttribute(gemm_hmma6<1>, cudaFuncAttributeMaxDynamicSharedMemorySize, GEMM6_SMEM);

    // 1) fused prep v2: wide fp16 converts + log2-domain bias table
    prep_fused<<<(NPREP + 255) / 256, 256>>>(queries, Wq, Wk, Wv, Wo, rel_emb,
                                             gA1h, gW1, gB);

    // 2) fused Q/K/V projections -> fp16 [z][bh][t][hs] (Q scaled by log2e/8)
    dim3 gGrid(D_ / 128, M_ / 128, 3);
    gemm_hmma6<1><<<gGrid, 256, GEMM6_SMEM>>>(gA1h, gW1, nullptr, gQKV1);

    // 3) fp16 attention -> fp16 AO
    dim3 aGrid(T_ / QT, B_ * NH_);
    attn_hmma<<<aGrid, 256, ATTN_SMEM>>>(gQKV1, gB, gAO1h);

    // 4) output projection (fp32 out)
    dim3 oGrid(D_ / 128, M_ / 128, 1);
    gemm_hmma6<0><<<oGrid, 256, GEMM6_SMEM>>>(gAO1h, gW1 + 3 * WOFF1, out, nullptr);
}